// round 5
// baseline (speedup 1.0000x reference)
#include <cuda_runtime.h>
#include <math.h>

#define FULLMASK 0xFFFFFFFFu

// ---------------- scratch (no allocations allowed) ----------------
__device__ double g_acc[8];           // 0..2: ifd0..2, 3..4: scr0..1
__device__ double g_main_part[32];    // per-batch -logp
__device__ float  g_norm2[32 * 448];  // f0 @0 (b*64), f1 @2048 (b*128), f2 @6144 (b*256)
__device__ int    g_sel0[64];
__device__ int    g_sel1[128];
__device__ int    g_cnt[128];         // per-batch: [b*4+0]=f0norm, +1=f1norm, +2=f2norm
__device__ int    g_setup_done;
__device__ int    g_done;             // ifd (896) + main (32) completions

// ---------------- threefry2x32-20 (exact JAX semantics) ----------------
__device__ __forceinline__ void tf2x32(unsigned k0, unsigned k1,
                                       unsigned x0, unsigned x1,
                                       unsigned& o0, unsigned& o1) {
  unsigned ks2 = 0x1BD11BDAu ^ k0 ^ k1;
#define TFR(r) { x0 += x1; x1 = (x1 << (r)) | (x1 >> (32 - (r))); x1 ^= x0; }
  x0 += k0; x1 += k1;
  TFR(13) TFR(15) TFR(26) TFR(6)   x0 += k1;  x1 += ks2 + 1u;
  TFR(17) TFR(29) TFR(16) TFR(24)  x0 += ks2; x1 += k0 + 2u;
  TFR(13) TFR(15) TFR(26) TFR(6)   x0 += k0;  x1 += k1 + 3u;
  TFR(17) TFR(29) TFR(16) TFR(24)  x0 += k1;  x1 += ks2 + 4u;
  TFR(13) TFR(15) TFR(26) TFR(6)   x0 += ks2; x1 += k0 + 5u;
#undef TFR
  o0 = x0; o1 = x1;
}

__device__ __forceinline__ void warp_red(float& s) {
  for (int o = 16; o; o >>= 1) s += __shfl_down_sync(FULLMASK, s, o);
}

// ---------------- setup: JAX channel permutations ----------------
__device__ void setup_body() {
  __shared__ unsigned keys[256];
  __shared__ int perm[256];
  int t = threadIdx.x;
#pragma unroll 1
  for (int i = 0; i < 2; i++) {
    unsigned kf0, kf1;
    tf2x32(0u, 42u, 0u, (unsigned)i, kf0, kf1);
    unsigned a0, a1, b0, b1;
    tf2x32(kf0, kf1, 0u, 2u, a0, a1);
    tf2x32(kf0, kf1, 1u, 3u, b0, b1);
    unsigned kt0 = a1, kt1 = b1;
    unsigned c0, c1, d0, d1;
    tf2x32(kt0, kt1, 0u, 2u, c0, c1);
    tf2x32(kt0, kt1, 1u, 3u, d0, d1);
    unsigned sk0 = c1, sk1 = d1;
    (void)a0; (void)b0; (void)c0; (void)d0;
    if (t < 128) {
      unsigned y0, y1;
      tf2x32(sk0, sk1, (unsigned)t, (unsigned)(t + 128), y0, y1);
      keys[t] = y0; keys[t + 128] = y1;
    }
    __syncthreads();
    unsigned my = keys[t];
    int rank = 0;
    for (int j = 0; j < 256; j++) {
      unsigned kj = keys[j];
      rank += (kj < my) || (kj == my && j < t);
    }
    perm[rank] = t;
    __syncthreads();
    if (i == 0) { if (t <  64) g_sel0[t] = perm[t]; }
    else        { if (t < 128) g_sel1[t] = perm[t]; }
    __syncthreads();
  }
  __threadfence();
  __syncthreads();
  if (t == 0) atomicExch(&g_setup_done, 1);
}

// ---------------- norms ----------------
// f0: 16 blocks/batch, 2 warps per row, 4 rows/block
__device__ void norm_f0(const float* __restrict__ f0, int b, int nb) {
  __shared__ float sh[8];
  int w = threadIdx.x >> 5, lane = threadIdx.x & 31;
  int r = nb * 4 + (w >> 1);
  const float4* p = (const float4*)(f0 + ((size_t)b * 64 + r) * 16384 + (w & 1) * 8192);
  float s = 0.f;
#pragma unroll 4
  for (int i = lane; i < 2048; i += 32) {
    float4 v = p[i];
    s += v.x * v.x + v.y * v.y + v.z * v.z + v.w * v.w;
  }
  warp_red(s);
  if (lane == 0) sh[w] = s;
  __syncthreads();
  if (threadIdx.x < 4)
    g_norm2[b * 64 + nb * 4 + threadIdx.x] = sh[2 * threadIdx.x] + sh[2 * threadIdx.x + 1];
  __threadfence();
  __syncthreads();
  if (threadIdx.x == 0) atomicAdd(&g_cnt[b * 4 + 0], 1);
}

// f1: 8 blocks/batch, warp per 2 rows
__device__ void norm_f1(const float* __restrict__ f1, int b, int nb) {
  int w = threadIdx.x >> 5, lane = threadIdx.x & 31;
  int r0 = nb * 16 + w * 2;
  const float* base = f1 + ((size_t)b * 128 + r0) * 4096;
#pragma unroll
  for (int rr = 0; rr < 2; rr++) {
    const float4* p = (const float4*)(base + rr * 4096);
    float s = 0.f;
#pragma unroll 4
    for (int i = lane; i < 1024; i += 32) {
      float4 v = p[i];
      s += v.x * v.x + v.y * v.y + v.z * v.z + v.w * v.w;
    }
    warp_red(s);
    if (lane == 0) g_norm2[2048 + b * 128 + r0 + rr] = s;
  }
  __threadfence();
  __syncthreads();
  if (threadIdx.x == 0) atomicAdd(&g_cnt[b * 4 + 1], 1);
}

// f2: 4 blocks/batch, warp per 8 rows
__device__ void norm_f2(const float* __restrict__ f2, int b, int nb) {
  int w = threadIdx.x >> 5, lane = threadIdx.x & 31;
  int r0 = nb * 64 + w * 8;
  const float* base = f2 + ((size_t)b * 256 + r0) * 1024;
#pragma unroll 1
  for (int rr = 0; rr < 8; rr++) {
    const float4* p = (const float4*)(base + rr * 1024);
    float s = 0.f;
#pragma unroll
    for (int i = lane; i < 256; i += 32) {
      float4 v = p[i];
      s += v.x * v.x + v.y * v.y + v.z * v.z + v.w * v.w;
    }
    warp_red(s);
    if (lane == 0) g_norm2[6144 + b * 256 + r0 + rr] = s;
  }
  __threadfence();
  __syncthreads();
  if (threadIdx.x == 0) atomicAdd(&g_cnt[b * 4 + 2], 1);
}

// ---------------- spin helpers ----------------
__device__ __forceinline__ void wait_norm(int b, int f, int tgt, bool need_setup) {
  if (threadIdx.x == 0) {
    volatile int* c = &g_cnt[b * 4 + f];
    while (*c < tgt) __nanosleep(64);
    if (need_setup) {
      volatile int* s = &g_setup_done;
      while (*s == 0) __nanosleep(64);
    }
    __threadfence();
  }
  __syncthreads();
}

template <bool HAS_T>
__device__ __forceinline__ void ifd_epilogue(float ifd, float scr, int AI, int AS,
                                             double (*shd)[8]) {
  double di = (double)ifd, ds = (double)scr;
  for (int o = 16; o; o >>= 1) {
    di += __shfl_down_sync(FULLMASK, di, o);
    if (HAS_T) ds += __shfl_down_sync(FULLMASK, ds, o);
  }
  int t = threadIdx.x, wid = t >> 5;
  if ((t & 31) == 0) { shd[0][wid] = di; if (HAS_T) shd[1][wid] = ds; }
  __syncthreads();
  if (t == 0) {
    double ti = 0.0, ts = 0.0;
    for (int i = 0; i < 8; i++) { ti += shd[0][i]; if (HAS_T) ts += shd[1][i]; }
    atomicAdd(&g_acc[AI], ti);
    if (HAS_T) atomicAdd(&g_acc[AS], ts);
    __threadfence();
    atomicAdd(&g_done, 1);
  }
}

// ---------------- IFD + SCR bodies ----------------
// feat0: C=64, HW=16384, W=128, VEC=4, 16 blocks/batch, teacher tile in smem
__device__ void ifd_f0(const float* __restrict__ f0, const float* __restrict__ f2,
                       int b, int pb) {
  __shared__ float ns[64];
  __shared__ int   sel[64];
  __shared__ unsigned char fl[64];
  __shared__ float tile[4096];     // 64 ch x 64 texels (2 teacher rows)
  __shared__ double shd[2][8];
  int t = threadIdx.x;
  wait_norm(b, 0, 16, true);
  if (t < 64) { ns[t] = g_norm2[b * 64 + t]; sel[t] = g_sel0[t]; }
  __syncthreads();
  if (t < 64) {
    float v = ns[t];
    int rank = 0;
#pragma unroll 4
    for (int j = 0; j < 64; j++) {
      float nj = ns[j];
      rank += (nj > v) || (nj == v && j < t);
    }
    fl[t] = (rank < 32) ? (unsigned char)0 : (unsigned char)1;
  }
  const float* tbase = f2 + (size_t)b * 256 * 1024 + pb * 2 * 32;
  for (int idx = t; idx < 4096; idx += 256) {
    int c = idx >> 6, j = idx & 63;
    tile[idx] = tbase[(size_t)sel[c] * 1024 + j];
  }
  __syncthreads();

  int p0 = pb * 1024 + t * 4;
  const float* xb = f0 + (size_t)b * 64 * 16384 + p0;
  int tvi = (t >> 7) * 32 + (t & 31);
  float sS0 = 0, sS1 = 0, sS2 = 0, sS3 = 0, sW0 = 0, sW1 = 0, sW2 = 0, sW3 = 0, scr = 0;
#pragma unroll 4
  for (int c = 0; c < 64; c++) {
    float4 q = *(const float4*)(xb + (size_t)c * 16384);
    float tv = tile[c * 64 + tvi];
    if (fl[c]) { sW0 += q.x; sW1 += q.y; sW2 += q.z; sW3 += q.w; }
    else       { sS0 += q.x; sS1 += q.y; sS2 += q.z; sS3 += q.w; }
    float d0 = q.x - tv, d1 = q.y - tv, d2 = q.z - tv, d3 = q.w - tv;
    scr += d0 * d0 + d1 * d1 + d2 * d2 + d3 * d3;
  }
  const float inv = 1.f / 32.f;
  float ifd = 0.f;
  float sS[4] = {sS0, sS1, sS2, sS3}, sW[4] = {sW0, sW1, sW2, sW3};
#pragma unroll
  for (int j = 0; j < 4; j++) {
    float aS = 1.f / (1.f + expf(-sS[j] * inv));
    float aW = 1.f / (1.f + expf(-sW[j] * inv));
    float d = aW - aS;
    ifd += d * d;
  }
  ifd_epilogue<true>(ifd, scr, 0, 3, shd);
}

// feat1: C=128, HW=4096, W=64, VEC=2, 8 blocks/batch, teacher via L2
__device__ void ifd_f1(const float* __restrict__ f1, const float* __restrict__ f2,
                       int b, int pb) {
  __shared__ float ns[128];
  __shared__ int   sel[128];
  __shared__ unsigned char fl[128];
  __shared__ double shd[2][8];
  int t = threadIdx.x;
  wait_norm(b, 1, 8, true);
  if (t < 128) { ns[t] = g_norm2[2048 + b * 128 + t]; sel[t] = g_sel1[t]; }
  __syncthreads();
  if (t < 128) {
    float v = ns[t];
    int rank = 0;
#pragma unroll 4
    for (int j = 0; j < 128; j++) {
      float nj = ns[j];
      rank += (nj > v) || (nj == v && j < t);
    }
    fl[t] = (rank < 64) ? (unsigned char)0 : (unsigned char)1;
  }
  __syncthreads();

  int p0 = pb * 512 + t * 2;
  const float* xb = f1 + (size_t)b * 128 * 4096 + p0;
  int tpix = (pb * 4 + (t >> 6)) * 32 + (t & 31);
  const float* tb = f2 + (size_t)b * 256 * 1024;
  float sS0 = 0, sS1 = 0, sW0 = 0, sW1 = 0, scr = 0;
#pragma unroll 4
  for (int c = 0; c < 128; c++) {
    float2 q = *(const float2*)(xb + (size_t)c * 4096);
    float tv = tb[(size_t)sel[c] * 1024 + tpix];
    if (fl[c]) { sW0 += q.x; sW1 += q.y; }
    else       { sS0 += q.x; sS1 += q.y; }
    float d0 = q.x - tv, d1 = q.y - tv;
    scr += d0 * d0 + d1 * d1;
  }
  const float inv = 1.f / 64.f;
  float aS0 = 1.f / (1.f + expf(-sS0 * inv)), aW0 = 1.f / (1.f + expf(-sW0 * inv));
  float aS1 = 1.f / (1.f + expf(-sS1 * inv)), aW1 = 1.f / (1.f + expf(-sW1 * inv));
  float d0 = aW0 - aS0, d1 = aW1 - aS1;
  ifd_epilogue<true>(d0 * d0 + d1 * d1, scr, 1, 4, shd);
}

// feat2: C=256, HW=1024, VEC=1, 4 blocks/batch, no teacher
__device__ void ifd_f2(const float* __restrict__ f2, int b, int pb) {
  __shared__ float ns[256];
  __shared__ unsigned char fl[256];
  __shared__ double shd[2][8];
  int t = threadIdx.x;
  wait_norm(b, 2, 4, false);
  ns[t] = g_norm2[6144 + b * 256 + t];
  __syncthreads();
  {
    float v = ns[t];
    int rank = 0;
#pragma unroll 4
    for (int j = 0; j < 256; j++) {
      float nj = ns[j];
      rank += (nj > v) || (nj == v && j < t);
    }
    fl[t] = (rank < 128) ? (unsigned char)0 : (unsigned char)1;
  }
  __syncthreads();

  int p0 = pb * 256 + t;
  const float* xb = f2 + (size_t)b * 256 * 1024 + p0;
  float sS = 0, sW = 0;
#pragma unroll 8
  for (int c = 0; c < 256; c++) {
    float v = xb[(size_t)c * 1024];
    if (fl[c]) sW += v; else sS += v;
  }
  const float inv = 1.f / 128.f;
  float aS = 1.f / (1.f + expf(-sS * inv));
  float aW = 1.f / (1.f + expf(-sW * inv));
  float d = aW - aS;
  ifd_epilogue<false>(d * d, 0.f, 2, 0, shd);
}

// ---------------- l_main: one block per batch ----------------
__device__ void main_body(const float* __restrict__ pred, const int* __restrict__ tgt, int b) {
  __shared__ float sh[8];
  __shared__ float shm;
  int t = threadIdx.x;
  const float* row = pred + b * 1000;
  float m = -1e30f;
  for (int i = t; i < 1000; i += 256) m = fmaxf(m, row[i]);
  for (int o = 16; o; o >>= 1) m = fmaxf(m, __shfl_down_sync(FULLMASK, m, o));
  if ((t & 31) == 0) sh[t >> 5] = m;
  __syncthreads();
  if (t == 0) {
    float mm = sh[0];
    for (int i = 1; i < 8; i++) mm = fmaxf(mm, sh[i]);
    shm = mm;
  }
  __syncthreads();
  m = shm;
  float s = 0.f;
  for (int i = t; i < 1000; i += 256) s += expf(row[i] - m);
  for (int o = 16; o; o >>= 1) s += __shfl_down_sync(FULLMASK, s, o);
  if ((t & 31) == 0) sh[t >> 5] = s;
  __syncthreads();
  if (t == 0) {
    float ss = 0.f;
    for (int i = 0; i < 8; i++) ss += sh[i];
    int tg = tgt[b];
    double lp = (double)(row[tg] - m) - log((double)ss);
    g_main_part[b] = -lp;
    __threadfence();
    atomicAdd(&g_done, 1);
  }
}

// ---------------- final block: wait for 928 completions, reduce, reset ----------------
__device__ void final_body(float* __restrict__ out) {
  int t = threadIdx.x;
  if (t == 0) {
    volatile int* d = &g_done;
    while (*d < 928) __nanosleep(128);
    __threadfence();
  }
  __syncthreads();
  if (t == 0) {
    double lm = 0.0;
    for (int i = 0; i < 32; i++) lm += g_main_part[i];
    double l_main = lm / 32.0;
    double ifd0 = g_acc[0] / (32.0 * 128.0 * 128.0);
    double ifd1 = g_acc[1] / (32.0 * 64.0 * 64.0);
    double ifd2 = g_acc[2] / (32.0 * 32.0 * 32.0);
    double l_ifd = (ifd0 + ifd1 + ifd2) / 3.0;
    double scr0 = g_acc[3] / (32.0 * 64.0 * 128.0 * 128.0);
    double scr1 = g_acc[4] / (32.0 * 128.0 * 64.0 * 64.0);
    double l_scr = (scr0 + scr1) / 2.0;
    double total = l_main + 0.015 * l_scr + 0.015 * l_ifd;
    out[0] = (float)total;
    out[1] = (float)l_main;
    out[2] = (float)l_scr;
    out[3] = (float)l_ifd;
  }
  __syncthreads();
  // reset state for next graph replay (initial state is also all-zero)
  if (t < 128) g_cnt[t] = 0;
  if (t == 0) {
    g_setup_done = 0;
    g_done = 0;
    for (int i = 0; i < 8; i++) g_acc[i] = 0.0;
  }
}

// ---------------- fused kernel ----------------
// bid 0: setup | 1 + b*56 + {0..15 f0n, 16..23 f1n, 24..27 f2n,
//                            28..43 f0i, 44..51 f1i, 52..55 f2i}
// 1793..1824: main | 1825: final
__global__ void __launch_bounds__(256) k_fused(
    const float* __restrict__ pred,
    const float* __restrict__ f0,
    const float* __restrict__ f1,
    const float* __restrict__ f2,
    const int* __restrict__ tgt,
    float* __restrict__ out) {
  int bid = blockIdx.x;
  if (bid == 0) { setup_body(); return; }
  bid -= 1;
  if (bid < 1792) {
    int b = bid / 56, r = bid % 56;
    if      (r < 16) norm_f0(f0, b, r);
    else if (r < 24) norm_f1(f1, b, r - 16);
    else if (r < 28) norm_f2(f2, b, r - 24);
    else if (r < 44) ifd_f0(f0, f2, b, r - 28);
    else if (r < 52) ifd_f1(f1, f2, b, r - 44);
    else             ifd_f2(f2, b, r - 52);
    return;
  }
  bid -= 1792;
  if (bid < 32) { main_body(pred, tgt, bid); return; }
  final_body(out);
}

extern "C" void kernel_launch(void* const* d_in, const int* in_sizes, int n_in,
                              void* d_out, int out_size) {
  const float* pred = (const float*)d_in[0];
  const float* f0   = (const float*)d_in[1];   // (32, 64, 128, 128)
  const float* f1   = (const float*)d_in[2];   // (32, 128, 64, 64)
  const float* f2   = (const float*)d_in[3];   // (32, 256, 32, 32)
  const int*   tgt  = (const int*)d_in[4];     // int32 (JAX x64 disabled)
  float* out = (float*)d_out;

  k_fused<<<1826, 256>>>(pred, f0, f1, f2, tgt, out);
}